// round 15
// baseline (speedup 1.0000x reference)
#include <cuda_runtime.h>
#include <cuda_fp16.h>
#include <cuda_bf16.h>

#define NT 256
#define NWARP 8
#define T 8                   // tiles (of 16 points) per warp
#define PTS (NWARP * T * 16)  // 1024 points per CTA
typedef unsigned int u32;

// ---- shared memory layout (float-index offsets) ----
#define OFF_BF   0                     // u32[84*9*32] = 24192
#define OFF_BIAS 24192                 // u32[84*12]  = 1008
#define OFF_H    25200                 // f32[24][PTS] = 24576
#define OFF_FR   (25200 + 24 * PTS)            // f32[100]
#define OFF_BWF  (OFF_FR + 100)                // u32[3*32] = 96 back_W B-frags
#define OFF_BB   (OFF_BWF + 96)                // f32[8] back_b padded
#define SMEM_FLOATS (OFF_BB + 8)
#define SMEM_BYTES (SMEM_FLOATS * 4)           // 199,840

__device__ __forceinline__ u32 packh2(float lo, float hi) {
    u32 r;
    asm("cvt.rn.f16x2.f32 %0, %1, %2;" : "=r"(r) : "f"(hi), "f"(lo));
    return r;
}
__device__ __forceinline__ u32 hswish2(u32 v) {
    u32 hv, t, r;
    asm("mul.rn.f16x2 %0, %1, %2;" : "=r"(hv) : "r"(v), "r"(0x38003800u));
    asm("tanh.approx.f16x2 %0, %1;" : "=r"(t) : "r"(hv));
    asm("fma.rn.f16x2 %0, %1, %2, %3;" : "=r"(r) : "r"(hv), "r"(t), "r"(hv));
    return r;
}
__device__ __forceinline__ u32 hadd2(u32 a, u32 b) {
    u32 r;
    asm("add.rn.f16x2 %0, %1, %2;" : "=r"(r) : "r"(a), "r"(b));
    return r;
}

__device__ __forceinline__ void mma16h_init(u32& d0, u32& d1,
                                            u32 a0, u32 a1, u32 a2, u32 a3,
                                            u32 b0, u32 b1, u32 c0, u32 c1) {
    asm volatile(
        "mma.sync.aligned.m16n8k16.row.col.f16.f16.f16.f16 "
        "{%0,%1}, {%2,%3,%4,%5}, {%6,%7}, {%8,%9};"
        : "=r"(d0), "=r"(d1)
        : "r"(a0), "r"(a1), "r"(a2), "r"(a3), "r"(b0), "r"(b1), "r"(c0), "r"(c1));
}
__device__ __forceinline__ void mma8h(u32& d0, u32& d1, u32 a0, u32 a1, u32 b) {
    asm volatile(
        "mma.sync.aligned.m16n8k8.row.col.f16.f16.f16.f16 "
        "{%0,%1}, {%2,%3}, {%4}, {%0,%1};"
        : "+r"(d0), "+r"(d1)
        : "r"(a0), "r"(a1), "r"(b));
}
__device__ __forceinline__ void mma16f(float* d, u32 a0, u32 a1, u32 a2, u32 a3,
                                       u32 b0, u32 b1) {
    asm volatile(
        "mma.sync.aligned.m16n8k16.row.col.f32.f16.f16.f32 "
        "{%0,%1,%2,%3}, {%4,%5,%6,%7}, {%8,%9}, {%0,%1,%2,%3};"
        : "+f"(d[0]), "+f"(d[1]), "+f"(d[2]), "+f"(d[3])
        : "r"(a0), "r"(a1), "r"(a2), "r"(a3), "r"(b0), "r"(b1));
}
__device__ __forceinline__ void mma8f(float* d, u32 a0, u32 a1, u32 b) {
    asm volatile(
        "mma.sync.aligned.m16n8k8.row.col.f32.f16.f16.f32 "
        "{%0,%1,%2,%3}, {%4,%5}, {%6}, {%0,%1,%2,%3};"
        : "+f"(d[0]), "+f"(d[1]), "+f"(d[2]), "+f"(d[3])
        : "r"(a0), "r"(a1), "r"(b));
}

// full 24x24 layer for one tile: Dh[3][2] = A * B + bias
__device__ __forceinline__ void layer_mma_h(u32 Dh[3][2], const u32 a[3][2],
                                            const u32 bf[9], const u32 bh[3]) {
#pragma unroll
    for (int ns = 0; ns < 3; ++ns) {
        mma16h_init(Dh[ns][0], Dh[ns][1],
                    a[0][0], a[0][1], a[1][0], a[1][1],
                    bf[0 + ns], bf[3 + ns], bh[ns], bh[ns]);
        mma8h(Dh[ns][0], Dh[ns][1], a[2][0], a[2][1], bf[6 + ns]);
    }
}

__global__ void __launch_bounds__(NT, 1)
reslinear_kernel(const float* __restrict__ x,
                 const float* __restrict__ fW, const float* __restrict__ fB,
                 const float* __restrict__ bW, const float* __restrict__ bB,
                 const float* __restrict__ Wn1, const float* __restrict__ bn1,
                 const float* __restrict__ Wl1, const float* __restrict__ bl1,
                 const float* __restrict__ Wn2, const float* __restrict__ bn2,
                 const float* __restrict__ Wl2, const float* __restrict__ bl2,
                 const float* __restrict__ Wn3, const float* __restrict__ bn3,
                 const float* __restrict__ Wl3, const float* __restrict__ bl3,
                 float* __restrict__ out, int n) {
    extern __shared__ float sm[];
    const int tid = threadIdx.x;
    u32* bfw = reinterpret_cast<u32*>(sm + OFF_BF);
    u32* bhs = reinterpret_cast<u32*>(sm + OFF_BIAS);
    u32* bwf = reinterpret_cast<u32*>(sm + OFF_BWF);

    // ---- stage params ----
    for (int w = tid; w < 80; w += NT) sm[OFF_FR + w] = fW[w];
    for (int w = tid; w < 20; w += NT) sm[OFF_FR + 80 + w] = fB[w];
    for (int w = tid; w < 8;  w += NT) sm[OFF_BB + w] = (w < 4) ? bB[w] : 0.f;
    for (int w = tid; w < 96; w += NT) {
        const int ks = w >> 5, lane = w & 31;
        const int k0 = ks * 8 + (lane & 3) * 2;
        const int nn = lane >> 2;
        float lo = (k0     < 20 && nn < 4) ? bW[k0 * 4 + nn]       : 0.f;
        float hi = (k0 + 1 < 20 && nn < 4) ? bW[(k0 + 1) * 4 + nn] : 0.f;
        bwf[w] = packh2(lo, hi);
    }
    // ---- pre-pack all 84 layer weights into mma B-fragment order (fp16) ----
    for (int w = tid; w < 24192; w += NT) {
        const int lane = w & 31;
        const int t9 = (w >> 5) % 9;
        const int L = w / 288;
        const int gb = L >> 2, j = L & 3;
        const float* W;
        if (gb < 16)      W = (j < 3) ? Wn1 + (gb * 3 + j) * 400 : Wl1 + gb * 400;
        else if (gb < 20) W = (j < 3) ? Wn2 + ((gb - 16) * 3 + j) * 400 : Wl2 + (gb - 16) * 400;
        else              W = (j < 3) ? Wn3 + j * 400 : Wl3;
        const int ks = t9 / 3, ns = t9 % 3;
        const int k0 = ks * 8 + (lane & 3) * 2;
        const int nn = ns * 8 + (lane >> 2);
        float lo = (k0     < 20 && nn < 20) ? W[k0 * 20 + nn]       : 0.f;
        float hi = (k0 + 1 < 20 && nn < 20) ? W[(k0 + 1) * 20 + nn] : 0.f;
        bfw[w] = packh2(lo, hi);
    }
    // ---- bias as f16x2, indexed [L][ns][tq] ----
    for (int w = tid; w < 1008; w += NT) {
        const int L = w / 12, r = w % 12;
        const int ns = r >> 2, tq = r & 3;
        const int gb = L >> 2, j = L & 3;
        const float* B;
        if (gb < 16)      B = (j < 3) ? bn1 + (gb * 3 + j) * 20 : bl1 + gb * 20;
        else if (gb < 20) B = (j < 3) ? bn2 + ((gb - 16) * 3 + j) * 20 : bl2 + (gb - 16) * 20;
        else              B = (j < 3) ? bn3 + j * 20 : bl3;
        const int c0 = ns * 8 + tq * 2;
        bhs[w] = packh2(c0 < 20 ? B[c0] : 0.f, c0 + 1 < 20 ? B[c0 + 1] : 0.f);
    }
    __syncthreads();

    const int lane = tid & 31, warp = tid >> 5;
    const int grp = lane >> 2, tq = lane & 3;
    const int base = blockIdx.x * PTS;
    float* H = sm + OFF_H;

    // ---- front layer: T/2 points per thread into H[24][PTS] ----
#pragma unroll
    for (int r = 0; r < T / 2; ++r) {
        const int slot = warp * (T * 16) + r * 32 + lane;
        const int g = base + slot;
        const float4 xv = reinterpret_cast<const float4*>(x)[(g < n) ? g : (n - 1)];
#pragma unroll
        for (int k = 0; k < 24; ++k) {
            float a = 0.f;
            if (k < 20) {
                a = sm[OFF_FR + 80 + k];
                a = fmaf(xv.x, sm[OFF_FR + 0 * 20 + k], a);
                a = fmaf(xv.y, sm[OFF_FR + 1 * 20 + k], a);
                a = fmaf(xv.z, sm[OFF_FR + 2 * 20 + k], a);
                a = fmaf(xv.w, sm[OFF_FR + 3 * 20 + k], a);
            }
            H[k * PTS + slot] = a;
        }
    }
    __syncthreads();

    float yD[T][4];   // fused back-projection accumulators (f32 D-frag per tile)

#pragma unroll
    for (int c = 0; c < 3; ++c) {
        // load h fragments from H for T tiles
        u32 af[T][3][2];
#pragma unroll
        for (int t = 0; t < T; ++t) {
            const int pb = warp * (T * 16) + t * 16 + grp;
#pragma unroll
            for (int ks = 0; ks < 3; ++ks) {
                const int kk = ks * 8 + tq * 2;
                af[t][ks][0] = packh2(H[kk * PTS + pb],     H[(kk + 1) * PTS + pb]);
                af[t][ks][1] = packh2(H[kk * PTS + pb + 8], H[(kk + 1) * PTS + pb + 8]);
            }
        }
        const int b0 = (c == 0) ? 0 : (c == 1) ? 16 : 20;
        const int nb = (c == 0) ? 16 : (c == 1) ? 4 : 1;

        for (int blk = 0; blk < nb; ++blk) {
            const int Lb = (b0 + blk) * 4;
            const u32* bfL = bfw + Lb * 288;
            const u32* bhL = bhs + Lb * 12;

            u32 cur[T][3][2];
#pragma unroll
            for (int t = 0; t < T; ++t)
#pragma unroll
                for (int ks = 0; ks < 3; ++ks) {
                    cur[t][ks][0] = af[t][ks][0];
                    cur[t][ks][1] = af[t][ks][1];
                }
            // ---- 3 net layers ----
#pragma unroll
            for (int j = 0; j < 3; ++j) {
                u32 bf[9];
#pragma unroll
                for (int t9 = 0; t9 < 9; ++t9) bf[t9] = bfL[j * 288 + t9 * 32 + lane];
                u32 bh[3];
#pragma unroll
                for (int ns = 0; ns < 3; ++ns) bh[ns] = bhL[j * 12 + ns * 4 + tq];
#pragma unroll
                for (int t = 0; t < T; ++t) {
                    u32 Dh[3][2];
                    layer_mma_h(Dh, cur[t], bf, bh);
#pragma unroll
                    for (int ns = 0; ns < 3; ++ns) {
                        cur[t][ns][0] = hswish2(Dh[ns][0]);
                        cur[t][ns][1] = hswish2(Dh[ns][1]);
                    }
                }
            }
            // ---- shortcut + residual: h' = o3 + swish(h @ Wl + bl) ----
            {
                u32 bf[9];
#pragma unroll
                for (int t9 = 0; t9 < 9; ++t9) bf[t9] = bfL[3 * 288 + t9 * 32 + lane];
                u32 bh[3];
#pragma unroll
                for (int ns = 0; ns < 3; ++ns) bh[ns] = bhL[36 + ns * 4 + tq];
#pragma unroll
                for (int t = 0; t < T; ++t) {
                    u32 Dh[3][2];
                    layer_mma_h(Dh, af[t], bf, bh);
#pragma unroll
                    for (int ns = 0; ns < 3; ++ns) {
                        af[t][ns][0] = hadd2(cur[t][ns][0], hswish2(Dh[ns][0]));
                        af[t][ns][1] = hadd2(cur[t][ns][1], hswish2(Dh[ns][1]));
                    }
                }
            }
        }

        // ---- fused back-projection: yD += chain_out @ back_W ----
        u32 bw0 = bwf[0 * 32 + lane], bw1 = bwf[1 * 32 + lane], bw2 = bwf[2 * 32 + lane];
        if (c == 0) {
            const float2 bbp = *reinterpret_cast<const float2*>(sm + OFF_BB + tq * 2);
#pragma unroll
            for (int t = 0; t < T; ++t) {
                yD[t][0] = bbp.x; yD[t][1] = bbp.y;
                yD[t][2] = bbp.x; yD[t][3] = bbp.y;
            }
        }
#pragma unroll
        for (int t = 0; t < T; ++t) {
            mma16f(yD[t], af[t][0][0], af[t][0][1], af[t][1][0], af[t][1][1], bw0, bw1);
            mma8f(yD[t], af[t][2][0], af[t][2][1], bw2);
        }
    }

    // ---- store: threads with tq<2 own real output columns (tq*2, tq*2+1) ----
    if (tq < 2) {
#pragma unroll
        for (int t = 0; t < T; ++t) {
            const int pb = base + warp * (T * 16) + t * 16 + grp;
            if (pb < n) {
                float2 v = make_float2(yD[t][0], yD[t][1]);
                *reinterpret_cast<float2*>(out + pb * 4 + tq * 2) = v;
            }
            if (pb + 8 < n) {
                float2 v = make_float2(yD[t][2], yD[t][3]);
                *reinterpret_cast<float2*>(out + (pb + 8) * 4 + tq * 2) = v;
            }
        }
    }
}

extern "C" void kernel_launch(void* const* d_in, const int* in_sizes, int n_in,
                              void* d_out, int out_size) {
    const float* x   = (const float*)d_in[0];
    const float* fW  = (const float*)d_in[1];
    const float* fB  = (const float*)d_in[2];
    const float* bW  = (const float*)d_in[3];
    const float* bB  = (const float*)d_in[4];
    const float* Wn1 = (const float*)d_in[5];
    const float* bn1 = (const float*)d_in[6];
    const float* Wl1 = (const float*)d_in[7];
    const float* bl1 = (const float*)d_in[8];
    const float* Wn2 = (const float*)d_in[9];
    const float* bn2 = (const float*)d_in[10];
    const float* Wl2 = (const float*)d_in[11];
    const float* bl2 = (const float*)d_in[12];
    const float* Wn3 = (const float*)d_in[13];
    const float* bn3 = (const float*)d_in[14];
    const float* Wl3 = (const float*)d_in[15];
    const float* bl3 = (const float*)d_in[16];
    float* out = (float*)d_out;

    const int n = in_sizes[0] / 4;

    cudaFuncSetAttribute(reslinear_kernel,
                         cudaFuncAttributeMaxDynamicSharedMemorySize, SMEM_BYTES);

    const int grid = (n + PTS - 1) / PTS;
    reslinear_kernel<<<grid, NT, SMEM_BYTES>>>(
        x, fW, fB, bW, bB,
        Wn1, bn1, Wl1, bl1,
        Wn2, bn2, Wl2, bl2,
        Wn3, bn3, Wl3, bl3,
        out, n);
}

// round 16
// speedup vs baseline: 1.1543x; 1.1543x over previous
#include <cuda_runtime.h>
#include <cuda_fp16.h>
#include <cuda_bf16.h>

#define NT 640
#define NWARP 20
#define T 2
#define PTS 640              // one point per thread staged; 2 tiles/warp
typedef unsigned int u32;

// ---- shared memory layout (4-byte-word offsets) ----
#define OFF_BF   0                     // u32[84*9*32] = 24192
#define OFF_BIAS 24192                 // u32[84*12]  = 1008 (bias*0.5, f16x2)
#define OFF_H16  25200                 // u32[PTS*12] = 7680 (h as f16 pairs)
#define OFF_FR   (25200 + PTS * 12)            // f32[100]
#define OFF_BWF  (OFF_FR + 100)                // u32[3*32] back_W B-frags
#define OFF_BB   (OFF_BWF + 96)                // f32[8] back_b padded
#define SMEM_WORDS (OFF_BB + 8)
#define SMEM_BYTES (SMEM_WORDS * 4)            // ~132KB

__device__ __forceinline__ u32 packh2(float lo, float hi) {
    u32 r;
    asm("cvt.rn.f16x2.f32 %0, %1, %2;" : "=r"(r) : "f"(hi), "f"(lo));
    return r;
}
// swish with PRE-SCALED input: v == x/2 already (weights folded by 0.5)
// swish(x) = v + v*tanh(v)
__device__ __forceinline__ u32 hswish2s(u32 v) {
    u32 t, r;
    asm("tanh.approx.f16x2 %0, %1;" : "=r"(t) : "r"(v));
    asm("fma.rn.f16x2 %0, %1, %2, %3;" : "=r"(r) : "r"(v), "r"(t), "r"(v));
    return r;
}
__device__ __forceinline__ u32 hadd2(u32 a, u32 b) {
    u32 r;
    asm("add.rn.f16x2 %0, %1, %2;" : "=r"(r) : "r"(a), "r"(b));
    return r;
}

__device__ __forceinline__ void mma16h_init(u32& d0, u32& d1,
                                            u32 a0, u32 a1, u32 a2, u32 a3,
                                            u32 b0, u32 b1, u32 c0, u32 c1) {
    asm volatile(
        "mma.sync.aligned.m16n8k16.row.col.f16.f16.f16.f16 "
        "{%0,%1}, {%2,%3,%4,%5}, {%6,%7}, {%8,%9};"
        : "=r"(d0), "=r"(d1)
        : "r"(a0), "r"(a1), "r"(a2), "r"(a3), "r"(b0), "r"(b1), "r"(c0), "r"(c1));
}
__device__ __forceinline__ void mma8h(u32& d0, u32& d1, u32 a0, u32 a1, u32 b) {
    asm volatile(
        "mma.sync.aligned.m16n8k8.row.col.f16.f16.f16.f16 "
        "{%0,%1}, {%2,%3}, {%4}, {%0,%1};"
        : "+r"(d0), "+r"(d1)
        : "r"(a0), "r"(a1), "r"(b));
}
__device__ __forceinline__ void mma16f(float* d, u32 a0, u32 a1, u32 a2, u32 a3,
                                       u32 b0, u32 b1) {
    asm volatile(
        "mma.sync.aligned.m16n8k16.row.col.f32.f16.f16.f32 "
        "{%0,%1,%2,%3}, {%4,%5,%6,%7}, {%8,%9}, {%0,%1,%2,%3};"
        : "+f"(d[0]), "+f"(d[1]), "+f"(d[2]), "+f"(d[3])
        : "r"(a0), "r"(a1), "r"(a2), "r"(a3), "r"(b0), "r"(b1));
}
__device__ __forceinline__ void mma8f(float* d, u32 a0, u32 a1, u32 b) {
    asm volatile(
        "mma.sync.aligned.m16n8k8.row.col.f32.f16.f16.f32 "
        "{%0,%1,%2,%3}, {%4,%5}, {%6}, {%0,%1,%2,%3};"
        : "+f"(d[0]), "+f"(d[1]), "+f"(d[2]), "+f"(d[3])
        : "r"(a0), "r"(a1), "r"(b));
}

// full 24x24 layer for one tile: Dh[3][2] = (A * B + bias) * 0.5  (scale folded)
__device__ __forceinline__ void layer_mma_h(u32 Dh[3][2], const u32 a[3][2],
                                            const u32 bf[9], const u32 bh[3]) {
#pragma unroll
    for (int ns = 0; ns < 3; ++ns) {
        mma16h_init(Dh[ns][0], Dh[ns][1],
                    a[0][0], a[0][1], a[1][0], a[1][1],
                    bf[0 + ns], bf[3 + ns], bh[ns], bh[ns]);
        mma8h(Dh[ns][0], Dh[ns][1], a[2][0], a[2][1], bf[6 + ns]);
    }
}

__global__ void __launch_bounds__(NT, 1)
reslinear_kernel(const float* __restrict__ x,
                 const float* __restrict__ fW, const float* __restrict__ fB,
                 const float* __restrict__ bW, const float* __restrict__ bB,
                 const float* __restrict__ Wn1, const float* __restrict__ bn1,
                 const float* __restrict__ Wl1, const float* __restrict__ bl1,
                 const float* __restrict__ Wn2, const float* __restrict__ bn2,
                 const float* __restrict__ Wl2, const float* __restrict__ bl2,
                 const float* __restrict__ Wn3, const float* __restrict__ bn3,
                 const float* __restrict__ Wl3, const float* __restrict__ bl3,
                 float* __restrict__ out, int n) {
    extern __shared__ float sm[];
    const int tid = threadIdx.x;
    u32* bfw = reinterpret_cast<u32*>(sm + OFF_BF);
    u32* bhs = reinterpret_cast<u32*>(sm + OFF_BIAS);
    u32* h16 = reinterpret_cast<u32*>(sm + OFF_H16);
    u32* bwf = reinterpret_cast<u32*>(sm + OFF_BWF);

    // ---- stage params ----
    for (int w = tid; w < 80; w += NT) sm[OFF_FR + w] = fW[w];
    for (int w = tid; w < 20; w += NT) sm[OFF_FR + 80 + w] = fB[w];
    for (int w = tid; w < 8;  w += NT) sm[OFF_BB + w] = (w < 4) ? bB[w] : 0.f;
    for (int w = tid; w < 96; w += NT) {
        const int ks = w >> 5, lane = w & 31;
        const int k0 = ks * 8 + (lane & 3) * 2;
        const int nn = lane >> 2;
        float lo = (k0     < 20 && nn < 4) ? bW[k0 * 4 + nn]       : 0.f;
        float hi = (k0 + 1 < 20 && nn < 4) ? bW[(k0 + 1) * 4 + nn] : 0.f;
        bwf[w] = packh2(lo, hi);
    }
    // ---- pre-pack 84 layer weights (SCALED by 0.5) into B-fragment order ----
    for (int w = tid; w < 24192; w += NT) {
        const int lane = w & 31;
        const int t9 = (w >> 5) % 9;
        const int L = w / 288;
        const int gb = L >> 2, j = L & 3;
        const float* W;
        if (gb < 16)      W = (j < 3) ? Wn1 + (gb * 3 + j) * 400 : Wl1 + gb * 400;
        else if (gb < 20) W = (j < 3) ? Wn2 + ((gb - 16) * 3 + j) * 400 : Wl2 + (gb - 16) * 400;
        else              W = (j < 3) ? Wn3 + j * 400 : Wl3;
        const int ks = t9 / 3, ns = t9 % 3;
        const int k0 = ks * 8 + (lane & 3) * 2;
        const int nn = ns * 8 + (lane >> 2);
        float lo = (k0     < 20 && nn < 20) ? 0.5f * W[k0 * 20 + nn]       : 0.f;
        float hi = (k0 + 1 < 20 && nn < 20) ? 0.5f * W[(k0 + 1) * 20 + nn] : 0.f;
        bfw[w] = packh2(lo, hi);
    }
    // ---- bias (SCALED by 0.5) as f16x2, indexed [L][ns][tq] ----
    for (int w = tid; w < 1008; w += NT) {
        const int L = w / 12, r = w % 12;
        const int ns = r >> 2, tq = r & 3;
        const int gb = L >> 2, j = L & 3;
        const float* B;
        if (gb < 16)      B = (j < 3) ? bn1 + (gb * 3 + j) * 20 : bl1 + gb * 20;
        else if (gb < 20) B = (j < 3) ? bn2 + ((gb - 16) * 3 + j) * 20 : bl2 + (gb - 16) * 20;
        else              B = (j < 3) ? bn3 + j * 20 : bl3;
        const int c0 = ns * 8 + tq * 2;
        bhs[w] = packh2(c0 < 20 ? 0.5f * B[c0] : 0.f,
                        c0 + 1 < 20 ? 0.5f * B[c0 + 1] : 0.f);
    }
    __syncthreads();

    const int lane = tid & 31, warp = tid >> 5;
    const int grp = lane >> 2, tq = lane & 3;
    const int base = blockIdx.x * PTS;

    // ---- front layer: one point per thread, h stored as f16 pairs ----
    {
        const int g = base + tid;
        const float4 xv = reinterpret_cast<const float4*>(x)[(g < n) ? g : (n - 1)];
#pragma unroll
        for (int q = 0; q < 12; ++q) {
            float a0 = 0.f, a1 = 0.f;
            const int k = 2 * q;
            if (k < 20) {
                a0 = sm[OFF_FR + 80 + k];
                a0 = fmaf(xv.x, sm[OFF_FR + 0 * 20 + k], a0);
                a0 = fmaf(xv.y, sm[OFF_FR + 1 * 20 + k], a0);
                a0 = fmaf(xv.z, sm[OFF_FR + 2 * 20 + k], a0);
                a0 = fmaf(xv.w, sm[OFF_FR + 3 * 20 + k], a0);
            }
            if (k + 1 < 20) {
                a1 = sm[OFF_FR + 80 + k + 1];
                a1 = fmaf(xv.x, sm[OFF_FR + 0 * 20 + k + 1], a1);
                a1 = fmaf(xv.y, sm[OFF_FR + 1 * 20 + k + 1], a1);
                a1 = fmaf(xv.z, sm[OFF_FR + 2 * 20 + k + 1], a1);
                a1 = fmaf(xv.w, sm[OFF_FR + 3 * 20 + k + 1], a1);
            }
            h16[tid * 12 + q] = packh2(a0, a1);
        }
    }
    __syncthreads();

    float yD[T][4];   // fused back-projection accumulators

#pragma unroll
    for (int c = 0; c < 3; ++c) {
        // load h fragments (single LDS.32 each; conflict-free by construction)
        u32 af[T][3][2];
#pragma unroll
        for (int t = 0; t < T; ++t) {
            const int pb = warp * (T * 16) + t * 16 + grp;
#pragma unroll
            for (int ks = 0; ks < 3; ++ks) {
                af[t][ks][0] = h16[pb * 12 + ks * 4 + tq];
                af[t][ks][1] = h16[(pb + 8) * 12 + ks * 4 + tq];
            }
        }
        const int b0 = (c == 0) ? 0 : (c == 1) ? 16 : 20;
        const int nb = (c == 0) ? 16 : (c == 1) ? 4 : 1;

        for (int blk = 0; blk < nb; ++blk) {
            const int Lb = (b0 + blk) * 4;
            const u32* bfL = bfw + Lb * 288;
            const u32* bhL = bhs + Lb * 12;

            u32 cur[T][3][2];
#pragma unroll
            for (int t = 0; t < T; ++t)
#pragma unroll
                for (int ks = 0; ks < 3; ++ks) {
                    cur[t][ks][0] = af[t][ks][0];
                    cur[t][ks][1] = af[t][ks][1];
                }
            // ---- 3 net layers ----
#pragma unroll
            for (int j = 0; j < 3; ++j) {
                u32 bf[9];
#pragma unroll
                for (int t9 = 0; t9 < 9; ++t9) bf[t9] = bfL[j * 288 + t9 * 32 + lane];
                u32 bh[3];
#pragma unroll
                for (int ns = 0; ns < 3; ++ns) bh[ns] = bhL[j * 12 + ns * 4 + tq];
#pragma unroll
                for (int t = 0; t < T; ++t) {
                    u32 Dh[3][2];
                    layer_mma_h(Dh, cur[t], bf, bh);
#pragma unroll
                    for (int ns = 0; ns < 3; ++ns) {
                        cur[t][ns][0] = hswish2s(Dh[ns][0]);
                        cur[t][ns][1] = hswish2s(Dh[ns][1]);
                    }
                }
            }
            // ---- shortcut + residual ----
            {
                u32 bf[9];
#pragma unroll
                for (int t9 = 0; t9 < 9; ++t9) bf[t9] = bfL[3 * 288 + t9 * 32 + lane];
                u32 bh[3];
#pragma unroll
                for (int ns = 0; ns < 3; ++ns) bh[ns] = bhL[36 + ns * 4 + tq];
#pragma unroll
                for (int t = 0; t < T; ++t) {
                    u32 Dh[3][2];
                    layer_mma_h(Dh, af[t], bf, bh);
#pragma unroll
                    for (int ns = 0; ns < 3; ++ns) {
                        af[t][ns][0] = hadd2(cur[t][ns][0], hswish2s(Dh[ns][0]));
                        af[t][ns][1] = hadd2(cur[t][ns][1], hswish2s(Dh[ns][1]));
                    }
                }
            }
        }

        // ---- fused back-projection: yD += chain_out @ back_W ----
        u32 bw0 = bwf[0 * 32 + lane], bw1 = bwf[1 * 32 + lane], bw2 = bwf[2 * 32 + lane];
        if (c == 0) {
            const float2 bbp = *reinterpret_cast<const float2*>(sm + OFF_BB + tq * 2);
#pragma unroll
            for (int t = 0; t < T; ++t) {
                yD[t][0] = bbp.x; yD[t][1] = bbp.y;
                yD[t][2] = bbp.x; yD[t][3] = bbp.y;
            }
        }
#pragma unroll
        for (int t = 0; t < T; ++t) {
            mma16f(yD[t], af[t][0][0], af[t][0][1], af[t][1][0], af[t][1][1], bw0, bw1);
            mma8f(yD[t], af[t][2][0], af[t][2][1], bw2);
        }
    }

    // ---- store: threads with tq<2 own real output columns (tq*2, tq*2+1) ----
    if (tq < 2) {
#pragma unroll
        for (int t = 0; t < T; ++t) {
            const int pb = base + warp * (T * 16) + t * 16 + grp;
            if (pb < n) {
                float2 v = make_float2(yD[t][0], yD[t][1]);
                *reinterpret_cast<float2*>(out + pb * 4 + tq * 2) = v;
            }
            if (pb + 8 < n) {
                float2 v = make_float2(yD[t][2], yD[t][3]);
                *reinterpret_cast<float2*>(out + (pb + 8) * 4 + tq * 2) = v;
            }
        }
    }
}

extern "C" void kernel_launch(void* const* d_in, const int* in_sizes, int n_in,
                              void* d_out, int out_size) {
    const float* x   = (const float*)d_in[0];
    const float* fW  = (const float*)d_in[1];
    const float* fB  = (const float*)d_in[2];
    const float* bW  = (const float*)d_in[3];
    const float* bB  = (const float*)d_in[4];
    const float* Wn1 = (const float*)d_in[5];
    const float* bn1 = (const float*)d_in[6];
    const float* Wl1 = (const float*)d_in[7];
    const float* bl1 = (const float*)d_in[8];
    const float* Wn2 = (const float*)d_in[9];
    const float* bn2 = (const float*)d_in[10];
    const float* Wl2 = (const float*)d_in[11];
    const float* bl2 = (const float*)d_in[12];
    const float* Wn3 = (const float*)d_in[13];
    const float* bn3 = (const float*)d_in[14];
    const float* Wl3 = (const float*)d_in[15];
    const float* bl3 = (const float*)d_in[16];
    float* out = (float*)d_out;

    const int n = in_sizes[0] / 4;

    cudaFuncSetAttribute(reslinear_kernel,
                         cudaFuncAttributeMaxDynamicSharedMemorySize, SMEM_BYTES);

    const int grid = (n + PTS - 1) / PTS;
    reslinear_kernel<<<grid, NT, SMEM_BYTES>>>(
        x, fW, fB, bW, bB,
        Wn1, bn1, Wl1, bl1,
        Wn2, bn2, Wl2, bl2,
        Wn3, bn3, Wl3, bl3,
        out, n);
}

// round 17
// speedup vs baseline: 1.2159x; 1.0533x over previous
#include <cuda_runtime.h>
#include <cuda_fp16.h>
#include <cuda_bf16.h>

#define NT 768
#define NWARP 24
#define T 2
#define PTS 768              // one point per thread staged; 2 tiles/warp
typedef unsigned int u32;

// ---- shared memory layout (4-byte-word offsets) ----
#define OFF_BF   0                     // u32[84*9*32] = 24192
#define OFF_BIAS 24192                 // u32[84*12]  = 1008 (bias*0.5, f16x2)
#define OFF_H16  25200                 // u32[PTS*12] (h as f16 pairs)
#define OFF_FR   (25200 + PTS * 12)            // f32[100]
#define OFF_BWF  (OFF_FR + 100)                // u32[3*32] back_W B-frags
#define OFF_BB   (OFF_BWF + 96)                // f32[8] back_b padded
#define SMEM_WORDS (OFF_BB + 8)
#define SMEM_BYTES (SMEM_WORDS * 4)            // ~139KB

__device__ __forceinline__ u32 packh2(float lo, float hi) {
    u32 r;
    asm("cvt.rn.f16x2.f32 %0, %1, %2;" : "=r"(r) : "f"(hi), "f"(lo));
    return r;
}
// swish with PRE-SCALED input: v == x/2 already (weights folded by 0.5)
__device__ __forceinline__ u32 hswish2s(u32 v) {
    u32 t, r;
    asm("tanh.approx.f16x2 %0, %1;" : "=r"(t) : "r"(v));
    asm("fma.rn.f16x2 %0, %1, %2, %3;" : "=r"(r) : "r"(v), "r"(t), "r"(v));
    return r;
}
__device__ __forceinline__ u32 hadd2(u32 a, u32 b) {
    u32 r;
    asm("add.rn.f16x2 %0, %1, %2;" : "=r"(r) : "r"(a), "r"(b));
    return r;
}

__device__ __forceinline__ void mma16h_init(u32& d0, u32& d1,
                                            u32 a0, u32 a1, u32 a2, u32 a3,
                                            u32 b0, u32 b1, u32 c0, u32 c1) {
    asm volatile(
        "mma.sync.aligned.m16n8k16.row.col.f16.f16.f16.f16 "
        "{%0,%1}, {%2,%3,%4,%5}, {%6,%7}, {%8,%9};"
        : "=r"(d0), "=r"(d1)
        : "r"(a0), "r"(a1), "r"(a2), "r"(a3), "r"(b0), "r"(b1), "r"(c0), "r"(c1));
}
__device__ __forceinline__ void mma8h(u32& d0, u32& d1, u32 a0, u32 a1, u32 b) {
    asm volatile(
        "mma.sync.aligned.m16n8k8.row.col.f16.f16.f16.f16 "
        "{%0,%1}, {%2,%3}, {%4}, {%0,%1};"
        : "+r"(d0), "+r"(d1)
        : "r"(a0), "r"(a1), "r"(b));
}
__device__ __forceinline__ void mma16f(float* d, u32 a0, u32 a1, u32 a2, u32 a3,
                                       u32 b0, u32 b1) {
    asm volatile(
        "mma.sync.aligned.m16n8k16.row.col.f32.f16.f16.f32 "
        "{%0,%1,%2,%3}, {%4,%5,%6,%7}, {%8,%9}, {%0,%1,%2,%3};"
        : "+f"(d[0]), "+f"(d[1]), "+f"(d[2]), "+f"(d[3])
        : "r"(a0), "r"(a1), "r"(a2), "r"(a3), "r"(b0), "r"(b1));
}
__device__ __forceinline__ void mma8f(float* d, u32 a0, u32 a1, u32 b) {
    asm volatile(
        "mma.sync.aligned.m16n8k8.row.col.f32.f16.f16.f32 "
        "{%0,%1,%2,%3}, {%4,%5}, {%6}, {%0,%1,%2,%3};"
        : "+f"(d[0]), "+f"(d[1]), "+f"(d[2]), "+f"(d[3])
        : "r"(a0), "r"(a1), "r"(b));
}

// full 24x24 layer for one tile: Dh[3][2] = (A * B + bias) * 0.5  (scale folded)
__device__ __forceinline__ void layer_mma_h(u32 Dh[3][2], const u32 a[3][2],
                                            const u32 bf[9], const u32 bh[3]) {
#pragma unroll
    for (int ns = 0; ns < 3; ++ns) {
        mma16h_init(Dh[ns][0], Dh[ns][1],
                    a[0][0], a[0][1], a[1][0], a[1][1],
                    bf[0 + ns], bf[3 + ns], bh[ns], bh[ns]);
        mma8h(Dh[ns][0], Dh[ns][1], a[2][0], a[2][1], bf[6 + ns]);
    }
}

__global__ void __launch_bounds__(NT, 1)
reslinear_kernel(const float* __restrict__ x,
                 const float* __restrict__ fW, const float* __restrict__ fB,
                 const float* __restrict__ bW, const float* __restrict__ bB,
                 const float* __restrict__ Wn1, const float* __restrict__ bn1,
                 const float* __restrict__ Wl1, const float* __restrict__ bl1,
                 const float* __restrict__ Wn2, const float* __restrict__ bn2,
                 const float* __restrict__ Wl2, const float* __restrict__ bl2,
                 const float* __restrict__ Wn3, const float* __restrict__ bn3,
                 const float* __restrict__ Wl3, const float* __restrict__ bl3,
                 float* __restrict__ out, int n) {
    extern __shared__ float sm[];
    const int tid = threadIdx.x;
    u32* bfw = reinterpret_cast<u32*>(sm + OFF_BF);
    u32* bhs = reinterpret_cast<u32*>(sm + OFF_BIAS);
    u32* h16 = reinterpret_cast<u32*>(sm + OFF_H16);
    u32* bwf = reinterpret_cast<u32*>(sm + OFF_BWF);

    // ---- stage params ----
    for (int w = tid; w < 80; w += NT) sm[OFF_FR + w] = fW[w];
    for (int w = tid; w < 20; w += NT) sm[OFF_FR + 80 + w] = fB[w];
    for (int w = tid; w < 8;  w += NT) sm[OFF_BB + w] = (w < 4) ? bB[w] : 0.f;
    for (int w = tid; w < 96; w += NT) {
        const int ks = w >> 5, lane = w & 31;
        const int k0 = ks * 8 + (lane & 3) * 2;
        const int nn = lane >> 2;
        float lo = (k0     < 20 && nn < 4) ? bW[k0 * 4 + nn]       : 0.f;
        float hi = (k0 + 1 < 20 && nn < 4) ? bW[(k0 + 1) * 4 + nn] : 0.f;
        bwf[w] = packh2(lo, hi);
    }
    // ---- pre-pack 84 layer weights (SCALED by 0.5) into B-fragment order ----
    for (int w = tid; w < 24192; w += NT) {
        const int lane = w & 31;
        const int t9 = (w >> 5) % 9;
        const int L = w / 288;
        const int gb = L >> 2, j = L & 3;
        const float* W;
        if (gb < 16)      W = (j < 3) ? Wn1 + (gb * 3 + j) * 400 : Wl1 + gb * 400;
        else if (gb < 20) W = (j < 3) ? Wn2 + ((gb - 16) * 3 + j) * 400 : Wl2 + (gb - 16) * 400;
        else              W = (j < 3) ? Wn3 + j * 400 : Wl3;
        const int ks = t9 / 3, ns = t9 % 3;
        const int k0 = ks * 8 + (lane & 3) * 2;
        const int nn = ns * 8 + (lane >> 2);
        float lo = (k0     < 20 && nn < 20) ? 0.5f * W[k0 * 20 + nn]       : 0.f;
        float hi = (k0 + 1 < 20 && nn < 20) ? 0.5f * W[(k0 + 1) * 20 + nn] : 0.f;
        bfw[w] = packh2(lo, hi);
    }
    // ---- bias (SCALED by 0.5) as f16x2, indexed [L][ns][tq] ----
    for (int w = tid; w < 1008; w += NT) {
        const int L = w / 12, r = w % 12;
        const int ns = r >> 2, tq = r & 3;
        const int gb = L >> 2, j = L & 3;
        const float* B;
        if (gb < 16)      B = (j < 3) ? bn1 + (gb * 3 + j) * 20 : bl1 + gb * 20;
        else if (gb < 20) B = (j < 3) ? bn2 + ((gb - 16) * 3 + j) * 20 : bl2 + (gb - 16) * 20;
        else              B = (j < 3) ? bn3 + j * 20 : bl3;
        const int c0 = ns * 8 + tq * 2;
        bhs[w] = packh2(c0 < 20 ? 0.5f * B[c0] : 0.f,
                        c0 + 1 < 20 ? 0.5f * B[c0 + 1] : 0.f);
    }
    __syncthreads();

    const int lane = tid & 31, warp = tid >> 5;
    const int grp = lane >> 2, tq = lane & 3;
    const int base = blockIdx.x * PTS;

    // ---- front layer: one point per thread, h stored as f16 pairs ----
    {
        const int g = base + tid;
        const float4 xv = reinterpret_cast<const float4*>(x)[(g < n) ? g : (n - 1)];
#pragma unroll
        for (int q = 0; q < 12; ++q) {
            float a0 = 0.f, a1 = 0.f;
            const int k = 2 * q;
            if (k < 20) {
                a0 = sm[OFF_FR + 80 + k];
                a0 = fmaf(xv.x, sm[OFF_FR + 0 * 20 + k], a0);
                a0 = fmaf(xv.y, sm[OFF_FR + 1 * 20 + k], a0);
                a0 = fmaf(xv.z, sm[OFF_FR + 2 * 20 + k], a0);
                a0 = fmaf(xv.w, sm[OFF_FR + 3 * 20 + k], a0);
            }
            if (k + 1 < 20) {
                a1 = sm[OFF_FR + 80 + k + 1];
                a1 = fmaf(xv.x, sm[OFF_FR + 0 * 20 + k + 1], a1);
                a1 = fmaf(xv.y, sm[OFF_FR + 1 * 20 + k + 1], a1);
                a1 = fmaf(xv.z, sm[OFF_FR + 2 * 20 + k + 1], a1);
                a1 = fmaf(xv.w, sm[OFF_FR + 3 * 20 + k + 1], a1);
            }
            h16[tid * 12 + q] = packh2(a0, a1);
        }
    }
    __syncthreads();

    float yD[T][4];   // fused back-projection accumulators (cold; spill-tolerant)

#pragma unroll
    for (int c = 0; c < 3; ++c) {
        // load h fragments (single LDS.32 each; conflict-free by construction)
        u32 af[T][3][2];
#pragma unroll
        for (int t = 0; t < T; ++t) {
            const int pb = warp * (T * 16) + t * 16 + grp;
#pragma unroll
            for (int ks = 0; ks < 3; ++ks) {
                af[t][ks][0] = h16[pb * 12 + ks * 4 + tq];
                af[t][ks][1] = h16[(pb + 8) * 12 + ks * 4 + tq];
            }
        }
        const int b0 = (c == 0) ? 0 : (c == 1) ? 16 : 20;
        const int nb = (c == 0) ? 16 : (c == 1) ? 4 : 1;

        for (int blk = 0; blk < nb; ++blk) {
            const int Lb = (b0 + blk) * 4;
            const u32* bfL = bfw + Lb * 288;
            const u32* bhL = bhs + Lb * 12;

            u32 cur[T][3][2];
#pragma unroll
            for (int t = 0; t < T; ++t)
#pragma unroll
                for (int ks = 0; ks < 3; ++ks) {
                    cur[t][ks][0] = af[t][ks][0];
                    cur[t][ks][1] = af[t][ks][1];
                }
            // ---- 3 net layers ----
#pragma unroll
            for (int j = 0; j < 3; ++j) {
                u32 bf[9];
#pragma unroll
                for (int t9 = 0; t9 < 9; ++t9) bf[t9] = bfL[j * 288 + t9 * 32 + lane];
                u32 bh[3];
#pragma unroll
                for (int ns = 0; ns < 3; ++ns) bh[ns] = bhL[j * 12 + ns * 4 + tq];
#pragma unroll
                for (int t = 0; t < T; ++t) {
                    u32 Dh[3][2];
                    layer_mma_h(Dh, cur[t], bf, bh);
#pragma unroll
                    for (int ns = 0; ns < 3; ++ns) {
                        cur[t][ns][0] = hswish2s(Dh[ns][0]);
                        cur[t][ns][1] = hswish2s(Dh[ns][1]);
                    }
                }
            }
            // ---- shortcut + residual ----
            {
                u32 bf[9];
#pragma unroll
                for (int t9 = 0; t9 < 9; ++t9) bf[t9] = bfL[3 * 288 + t9 * 32 + lane];
                u32 bh[3];
#pragma unroll
                for (int ns = 0; ns < 3; ++ns) bh[ns] = bhL[36 + ns * 4 + tq];
#pragma unroll
                for (int t = 0; t < T; ++t) {
                    u32 Dh[3][2];
                    layer_mma_h(Dh, af[t], bf, bh);
#pragma unroll
                    for (int ns = 0; ns < 3; ++ns) {
                        af[t][ns][0] = hadd2(cur[t][ns][0], hswish2s(Dh[ns][0]));
                        af[t][ns][1] = hadd2(cur[t][ns][1], hswish2s(Dh[ns][1]));
                    }
                }
            }
        }

        // ---- fused back-projection: yD += chain_out @ back_W ----
        u32 bw0 = bwf[0 * 32 + lane], bw1 = bwf[1 * 32 + lane], bw2 = bwf[2 * 32 + lane];
        if (c == 0) {
            const float2 bbp = *reinterpret_cast<const float2*>(sm + OFF_BB + tq * 2);
#pragma unroll
            for (int t = 0; t < T; ++t) {
                yD[t][0] = bbp.x; yD[t][1] = bbp.y;
                yD[t][2] = bbp.x; yD[t][3] = bbp.y;
            }
        }
#pragma unroll
        for (int t = 0; t < T; ++t) {
            mma16f(yD[t], af[t][0][0], af[t][0][1], af[t][1][0], af[t][1][1], bw0, bw1);
            mma8f(yD[t], af[t][2][0], af[t][2][1], bw2);
        }
    }

    // ---- store: threads with tq<2 own real output columns (tq*2, tq*2+1) ----
    if (tq < 2) {
#pragma unroll
        for (int t = 0; t < T; ++t) {
            const int pb = base + warp * (T * 16) + t * 16 + grp;
            if (pb < n) {
                float2 v = make_float2(yD[t][0], yD[t][1]);
                *reinterpret_cast<float2*>(out + pb * 4 + tq * 2) = v;
            }
            if (pb + 8 < n) {
                float2 v = make_float2(yD[t][2], yD[t][3]);
                *reinterpret_cast<float2*>(out + (pb + 8) * 4 + tq * 2) = v;
            }
        }
    }
}

extern "C" void kernel_launch(void* const* d_in, const int* in_sizes, int n_in,
                              void* d_out, int out_size) {
    const float* x   = (const float*)d_in[0];
    const float* fW  = (const float*)d_in[1];
    const float* fB  = (const float*)d_in[2];
    const float* bW  = (const float*)d_in[3];
    const float* bB  = (const float*)d_in[4];
    const float* Wn1 = (const float*)d_in[5];
    const float* bn1 = (const float*)d_in[6];
    const float* Wl1 = (const float*)d_in[7];
    const float* bl1 = (const float*)d_in[8];
    const float* Wn2 = (const float*)d_in[9];
    const float* bn2 = (const float*)d_in[10];
    const float* Wl2 = (const float*)d_in[11];
    const float* bl2 = (const float*)d_in[12];
    const float* Wn3 = (const float*)d_in[13];
    const float* bn3 = (const float*)d_in[14];
    const float* Wl3 = (const float*)d_in[15];
    const float* bl3 = (const float*)d_in[16];
    float* out = (float*)d_out;

    const int n = in_sizes[0] / 4;

    cudaFuncSetAttribute(reslinear_kernel,
                         cudaFuncAttributeMaxDynamicSharedMemorySize, SMEM_BYTES);

    const int grid = (n + PTS - 1) / PTS;
    reslinear_kernel<<<grid, NT, SMEM_BYTES>>>(
        x, fW, fB, bW, bB,
        Wn1, bn1, Wl1, bl1,
        Wn2, bn2, Wl2, bl2,
        Wn3, bn3, Wl3, bl3,
        out, n);
}